// round 8
// baseline (speedup 1.0000x reference)
#include <cuda_runtime.h>
#include <cuda_fp16.h>
#include <mma.h>

using namespace nvcuda;

#define TT 4096
#define DD 2048
#define FF 4096
#define EE 8
#define XX 2
#define AA (TT * XX)

#define BM 128
#define BN 64
#define BK 32
#define ALD 40                        // A smem ldm (halves), 80B rows
#define BLD 72                        // B smem ldm (halves), 144B rows
#define SLD 20                        // scratch ldm (floats)
#define MAX_TILES (AA / BM + EE)      // 72

// smem byte offsets (gateup): A[2] @0 (10240 ea), B[2][2] @20480 (4608 ea) -> 38912 total
#define A_BYTES (BM * ALD * 2)            // 10240
#define B_BYTES (BK * BLD * 2)            // 4608
#define GUP_SMEM (2 * A_BYTES + 4 * B_BYTES)
#define DWN_SMEM (2 * A_BYTES + 2 * B_BYTES)

// ---------------- scratch (device globals; ~160MB, under proven 192MB envelope) ----------------
__device__ __align__(128) __half g_x16[(size_t)AA * DD];   // sorted x, fp16 (32MB)
__device__ __align__(128) __half g_h16[(size_t)AA * FF];   // silu(g)*u, fp16 (64MB)
__device__ __align__(128) float g_down[(size_t)AA * DD];   // down output (64MB)
__device__ int g_tile_e[MAX_TILES];
__device__ int g_tile_row0[MAX_TILES];
__device__ int g_tile_cnt[MAX_TILES];
__device__ int g_num_tiles;
__device__ int g_tok[AA];
__device__ int g_pos[AA];

// ---------------- setup: counting sort + tile table (proven) ----------------
__global__ void setup_kernel(const int* __restrict__ sel) {
    __shared__ int cnt[EE];
    __shared__ int cur[EE];
    const int tid = threadIdx.x;
    if (tid < EE) cnt[tid] = 0;
    __syncthreads();
    for (int a = tid; a < AA; a += blockDim.x) atomicAdd(&cnt[sel[a]], 1);
    __syncthreads();
    if (tid == 0) {
        int o = 0, nt = 0;
        for (int e = 0; e < EE; e++) {
            cur[e] = o;
            const int c = cnt[e];
            for (int m = 0; m < c; m += BM) {
                g_tile_e[nt] = e;
                g_tile_row0[nt] = o + m;
                g_tile_cnt[nt] = (c - m < BM) ? (c - m) : BM;
                nt++;
            }
            o += c;
        }
        g_num_tiles = nt;
    }
    __syncthreads();
    for (int a = tid; a < AA; a += blockDim.x) {
        const int e = sel[a];
        const int p = atomicAdd(&cur[e], 1);
        g_pos[a] = p;
        g_tok[p] = a >> 1;
    }
}

__device__ __forceinline__ uint4 pack8(const float4 v0, const float4 v1) {
    __half h[8] = {__float2half_rn(v0.x), __float2half_rn(v0.y),
                   __float2half_rn(v0.z), __float2half_rn(v0.w),
                   __float2half_rn(v1.x), __float2half_rn(v1.y),
                   __float2half_rn(v1.z), __float2half_rn(v1.w)};
    return *(const uint4*)h;
}

// ---------------- convert x: gather sorted rows -> fp16 ----------------
__global__ void convert_x(const float* __restrict__ x) {
    const int p = blockIdx.x;
    const float4* src = (const float4*)(x + (size_t)g_tok[p] * DD);
    uint4* dst = (uint4*)(g_x16 + (size_t)p * DD);
    for (int i = threadIdx.x; i < DD / 8; i += 256)
        dst[i] = pack8(src[2 * i], src[2 * i + 1]);
}

// ================= fused gate+up GEMM (wmma fp16, BK=32) =================
__global__ __launch_bounds__(256) void gemm_gateup(const float* __restrict__ Wg,
                                                   const float* __restrict__ Wu) {
    __shared__ __align__(16) char sraw[GUP_SMEM];
    __half* Asm[2] = {(__half*)sraw, (__half*)(sraw + A_BYTES)};
    // B: [buf][mat]  mat 0=gate 1=up
    __half* Bsm[2][2] = {
        {(__half*)(sraw + 2 * A_BYTES), (__half*)(sraw + 2 * A_BYTES + B_BYTES)},
        {(__half*)(sraw + 2 * A_BYTES + 2 * B_BYTES), (__half*)(sraw + 2 * A_BYTES + 3 * B_BYTES)}};
    float* scr = (float*)sraw;  // epilogue overlay on A buffers (post-loop only)

    const int mt = blockIdx.x;
    if (mt >= g_num_tiles) return;
    const int e = g_tile_e[mt];
    const int row0 = g_tile_row0[mt];
    const int cnt = g_tile_cnt[mt];
    const int n0 = blockIdx.y * BN;
    const int tid = threadIdx.x;
    const int wid = tid >> 5;
    const int lane = tid & 31;
    const int wm0 = (wid & 3) * 32;
    const int wn0 = (wid >> 2) * 32;

    // A loader: 128 rows x 2 segments of 16 halves (32B)
    const int lr = tid >> 1, lc = (tid & 1) * 16;
    const int rowc = (lr < cnt) ? lr : 0;
    const __half* pa = g_x16 + (size_t)(row0 + rowc) * DD + lc;
    const int aoff = lr * ALD + lc;
    // B loader: 32 k-rows x 8 chunks of 8 floats
    const int bk = tid >> 3, bn = (tid & 7) * 8;
    const float* pg = Wg + ((size_t)e * DD + bk) * FF + n0 + bn;
    const float* pu = Wu + ((size_t)e * DD + bk) * FF + n0 + bn;
    const int boff = bk * BLD + bn;

    wmma::fragment<wmma::accumulator, 16, 16, 16, float> accg[2][2], accu[2][2];
#pragma unroll
    for (int mi = 0; mi < 2; mi++)
#pragma unroll
        for (int nj = 0; nj < 2; nj++) {
            wmma::fill_fragment(accg[mi][nj], 0.0f);
            wmma::fill_fragment(accu[mi][nj], 0.0f);
        }

    const int NC = DD / BK;  // 64

    // prime buffer 0
    {
        *(uint4*)&Asm[0][aoff] = *(const uint4*)pa;
        *(uint4*)&Asm[0][aoff + 8] = *(const uint4*)(pa + 8);
        *(uint4*)&Bsm[0][0][boff] = pack8(*(const float4*)pg, *(const float4*)(pg + 4));
        *(uint4*)&Bsm[0][1][boff] = pack8(*(const float4*)pu, *(const float4*)(pu + 4));
    }
    __syncthreads();

    for (int c = 0; c < NC; c++) {
        const int buf = c & 1;
        uint4 va0, va1;
        float4 vg0, vg1, vu0, vu1;
        if (c + 1 < NC) {
            const __half* pan = pa + (c + 1) * BK;
            va0 = *(const uint4*)pan;
            va1 = *(const uint4*)(pan + 8);
            const float* pgn = pg + (size_t)(c + 1) * BK * FF;
            const float* pun = pu + (size_t)(c + 1) * BK * FF;
            vg0 = *(const float4*)pgn; vg1 = *(const float4*)(pgn + 4);
            vu0 = *(const float4*)pun; vu1 = *(const float4*)(pun + 4);
        }

#pragma unroll
        for (int ks = 0; ks < 2; ks++) {
            wmma::fragment<wmma::matrix_a, 16, 16, 16, __half, wmma::row_major> aF[2];
            wmma::fragment<wmma::matrix_b, 16, 16, 16, __half, wmma::row_major> bg[2], bu[2];
#pragma unroll
            for (int mi = 0; mi < 2; mi++)
                wmma::load_matrix_sync(aF[mi], &Asm[buf][(wm0 + mi * 16) * ALD + ks * 16], ALD);
#pragma unroll
            for (int nj = 0; nj < 2; nj++) {
                wmma::load_matrix_sync(bg[nj], &Bsm[buf][0][ks * 16 * BLD + wn0 + nj * 16], BLD);
                wmma::load_matrix_sync(bu[nj], &Bsm[buf][1][ks * 16 * BLD + wn0 + nj * 16], BLD);
            }
#pragma unroll
            for (int mi = 0; mi < 2; mi++)
#pragma unroll
                for (int nj = 0; nj < 2; nj++) {
                    wmma::mma_sync(accg[mi][nj], aF[mi], bg[nj], accg[mi][nj]);
                    wmma::mma_sync(accu[mi][nj], aF[mi], bu[nj], accu[mi][nj]);
                }
        }

        if (c + 1 < NC) {
            const int nb = (c + 1) & 1;
            __syncthreads();  // all warps done reading buf nb from two chunks ago
            *(uint4*)&Asm[nb][aoff] = va0;
            *(uint4*)&Asm[nb][aoff + 8] = va1;
            *(uint4*)&Bsm[nb][0][boff] = pack8(vg0, vg1);
            *(uint4*)&Bsm[nb][1][boff] = pack8(vu0, vu1);
        }
        __syncthreads();
    }

    // epilogue: h16 = silu(g) * u, via per-warp scratch (overlaid on A smem)
    float* myscr = scr + wid * (16 * SLD);
    const int er = lane >> 1, ec = (lane & 1) * 8;
#pragma unroll
    for (int mi = 0; mi < 2; mi++)
#pragma unroll
        for (int nj = 0; nj < 2; nj++) {
            float gv[8], uv[8];
            wmma::store_matrix_sync(myscr, accg[mi][nj], SLD, wmma::mem_row_major);
            __syncwarp();
#pragma unroll
            for (int q = 0; q < 8; q++) gv[q] = myscr[er * SLD + ec + q];
            __syncwarp();
            wmma::store_matrix_sync(myscr, accu[mi][nj], SLD, wmma::mem_row_major);
            __syncwarp();
#pragma unroll
            for (int q = 0; q < 8; q++) uv[q] = myscr[er * SLD + ec + q];
            __syncwarp();
            const int rin = wm0 + mi * 16 + er;
            if (rin < cnt) {
                __half o[8];
#pragma unroll
                for (int q = 0; q < 8; q++)
                    o[q] = __float2half_rn((gv[q] / (1.0f + __expf(-gv[q]))) * uv[q]);
                *(uint4*)(g_h16 + (size_t)(row0 + rin) * FF + n0 + wn0 + nj * 16 + ec) =
                    *(const uint4*)o;
            }
        }
}

// ================= down GEMM (wmma fp16, BK=32) =================
__global__ __launch_bounds__(256) void gemm_down(const float* __restrict__ Wd) {
    __shared__ __align__(16) char sraw[DWN_SMEM];
    __half* Asm[2] = {(__half*)sraw, (__half*)(sraw + A_BYTES)};
    __half* Bsm[2] = {(__half*)(sraw + 2 * A_BYTES), (__half*)(sraw + 2 * A_BYTES + B_BYTES)};
    float* scr = (float*)sraw;

    const int mt = blockIdx.x;
    if (mt >= g_num_tiles) return;
    const int e = g_tile_e[mt];
    const int row0 = g_tile_row0[mt];
    const int cnt = g_tile_cnt[mt];
    const int n0 = blockIdx.y * BN;
    const int tid = threadIdx.x;
    const int wid = tid >> 5;
    const int lane = tid & 31;
    const int wm0 = (wid & 3) * 32;
    const int wn0 = (wid >> 2) * 32;

    const int lr = tid >> 1, lc = (tid & 1) * 16;
    const int rowc = (lr < cnt) ? lr : 0;
    const __half* pa = g_h16 + (size_t)(row0 + rowc) * FF + lc;
    const int aoff = lr * ALD + lc;
    const int bk = tid >> 3, bn = (tid & 7) * 8;
    const float* pb = Wd + ((size_t)e * FF + bk) * DD + n0 + bn;
    const int boff = bk * BLD + bn;

    wmma::fragment<wmma::accumulator, 16, 16, 16, float> acc[2][2];
#pragma unroll
    for (int mi = 0; mi < 2; mi++)
#pragma unroll
        for (int nj = 0; nj < 2; nj++) wmma::fill_fragment(acc[mi][nj], 0.0f);

    const int NC = FF / BK;  // 128

    {
        *(uint4*)&Asm[0][aoff] = *(const uint4*)pa;
        *(uint4*)&Asm[0][aoff + 8] = *(const uint4*)(pa + 8);
        *(uint4*)&Bsm[0][boff] = pack8(*(const float4*)pb, *(const float4*)(pb + 4));
    }
    __syncthreads();

    for (int c = 0; c < NC; c++) {
        const int buf = c & 1;
        uint4 va0, va1;
        float4 vb0, vb1;
        if (c + 1 < NC) {
            const __half* pan = pa + (c + 1) * BK;
            va0 = *(const uint4*)pan;
            va1 = *(const uint4*)(pan + 8);
            const float* pbn = pb + (size_t)(c + 1) * BK * DD;
            vb0 = *(const float4*)pbn; vb1 = *(const float4*)(pbn + 4);
        }

#pragma unroll
        for (int ks = 0; ks < 2; ks++) {
            wmma::fragment<wmma::matrix_a, 16, 16, 16, __half, wmma::row_major> aF[2];
            wmma::fragment<wmma::matrix_b, 16, 16, 16, __half, wmma::row_major> bd[2];
#pragma unroll
            for (int mi = 0; mi < 2; mi++)
                wmma::load_matrix_sync(aF[mi], &Asm[buf][(wm0 + mi * 16) * ALD + ks * 16], ALD);
#pragma unroll
            for (int nj = 0; nj < 2; nj++)
                wmma::load_matrix_sync(bd[nj], &Bsm[buf][ks * 16 * BLD + wn0 + nj * 16], BLD);
#pragma unroll
            for (int mi = 0; mi < 2; mi++)
#pragma unroll
                for (int nj = 0; nj < 2; nj++)
                    wmma::mma_sync(acc[mi][nj], aF[mi], bd[nj], acc[mi][nj]);
        }

        if (c + 1 < NC) {
            const int nb = (c + 1) & 1;
            __syncthreads();
            *(uint4*)&Asm[nb][aoff] = va0;
            *(uint4*)&Asm[nb][aoff + 8] = va1;
            *(uint4*)&Bsm[nb][boff] = pack8(vb0, vb1);
        }
        __syncthreads();
    }

    float* myscr = scr + wid * (16 * SLD);
    const int er = lane >> 1, ec = (lane & 1) * 8;
#pragma unroll
    for (int mi = 0; mi < 2; mi++)
#pragma unroll
        for (int nj = 0; nj < 2; nj++) {
            wmma::store_matrix_sync(myscr, acc[mi][nj], SLD, wmma::mem_row_major);
            __syncwarp();
            float o[8];
#pragma unroll
            for (int q = 0; q < 8; q++) o[q] = myscr[er * SLD + ec + q];
            __syncwarp();
            const int rin = wm0 + mi * 16 + er;
            if (rin < cnt) {
                float* dst = g_down + (size_t)(row0 + rin) * DD + n0 + wn0 + nj * 16 + ec;
                *(float4*)dst = make_float4(o[0], o[1], o[2], o[3]);
                *(float4*)(dst + 4) = make_float4(o[4], o[5], o[6], o[7]);
            }
        }
}

// ---------------- combine (proven) ----------------
__global__ void combine_kernel(const float* __restrict__ rw, float* __restrict__ out) {
    const int i = blockIdx.x * blockDim.x + threadIdx.x;
    if (i >= TT * (DD / 4)) return;
    const int t = i / (DD / 4);
    const int c = (i % (DD / 4)) * 4;
    const int p0 = g_pos[t * 2 + 0];
    const int p1 = g_pos[t * 2 + 1];
    const float w0 = rw[t * 2 + 0];
    const float w1 = rw[t * 2 + 1];
    const float4 a = *(const float4*)&g_down[(size_t)p0 * DD + c];
    const float4 b = *(const float4*)&g_down[(size_t)p1 * DD + c];
    float4 o;
    o.x = w0 * a.x + w1 * b.x;
    o.y = w0 * a.y + w1 * b.y;
    o.z = w0 * a.z + w1 * b.z;
    o.w = w0 * a.w + w1 * b.w;
    *(float4*)&out[(size_t)t * DD + c] = o;
}

extern "C" void kernel_launch(void* const* d_in, const int* in_sizes, int n_in,
                              void* d_out, int out_size) {
    const float* x   = (const float*)d_in[0];
    const float* rw  = (const float*)d_in[1];
    const int*   sel = (const int*)d_in[2];
    const float* Wg  = (const float*)d_in[3];
    const float* Wu  = (const float*)d_in[4];
    const float* Wd  = (const float*)d_in[5];
    float* out = (float*)d_out;

    setup_kernel<<<1, 256>>>(sel);
    convert_x<<<AA, 256>>>(x);
    gemm_gateup<<<dim3(MAX_TILES, FF / BN), 256>>>(Wg, Wu);
    gemm_down<<<dim3(MAX_TILES, DD / BN), 256>>>(Wd);
    combine_kernel<<<(TT * (DD / 4) + 255) / 256, 256>>>(rw, out);
}

// round 9
// speedup vs baseline: 1.1285x; 1.1285x over previous
#include <cuda_runtime.h>
#include <cuda_fp16.h>
#include <mma.h>

using namespace nvcuda;

#define TT 4096
#define DD 2048
#define FF 4096
#define EE 8
#define XX 2
#define AA (TT * XX)

#define BM 128
#define BN 64
#define BK 16
#define ALD 24                        // A smem ldm (halves), 48B rows
#define BLD 72                        // B smem ldm (halves), 144B rows
#define SLD 20                        // scratch ldm (floats)
#define MAX_TILES (AA / BM + EE)      // 72

// ---------------- scratch (device globals; ~160MB) ----------------
__device__ __align__(128) __half g_x16[(size_t)AA * DD];   // sorted x, fp16
__device__ __align__(128) __half g_h16[(size_t)AA * FF];   // silu(g)*u, fp16
__device__ __align__(128) float g_down[(size_t)AA * DD];   // down output, fp32
__device__ int g_tile_e[MAX_TILES];
__device__ int g_tile_row0[MAX_TILES];
__device__ int g_tile_cnt[MAX_TILES];
__device__ int g_num_tiles;
__device__ int g_tok[AA];
__device__ int g_pos[AA];

// ---------------- setup: counting sort + tile table (proven) ----------------
__global__ void setup_kernel(const int* __restrict__ sel) {
    __shared__ int cnt[EE];
    __shared__ int cur[EE];
    const int tid = threadIdx.x;
    if (tid < EE) cnt[tid] = 0;
    __syncthreads();
    for (int a = tid; a < AA; a += blockDim.x) atomicAdd(&cnt[sel[a]], 1);
    __syncthreads();
    if (tid == 0) {
        int o = 0, nt = 0;
        for (int e = 0; e < EE; e++) {
            cur[e] = o;
            const int c = cnt[e];
            for (int m = 0; m < c; m += BM) {
                g_tile_e[nt] = e;
                g_tile_row0[nt] = o + m;
                g_tile_cnt[nt] = (c - m < BM) ? (c - m) : BM;
                nt++;
            }
            o += c;
        }
        g_num_tiles = nt;
    }
    __syncthreads();
    for (int a = tid; a < AA; a += blockDim.x) {
        const int e = sel[a];
        const int p = atomicAdd(&cur[e], 1);
        g_pos[a] = p;
        g_tok[p] = a >> 1;
    }
}

__device__ __forceinline__ uint4 pack8(const float4 v0, const float4 v1) {
    __half h[8] = {__float2half_rn(v0.x), __float2half_rn(v0.y),
                   __float2half_rn(v0.z), __float2half_rn(v0.w),
                   __float2half_rn(v1.x), __float2half_rn(v1.y),
                   __float2half_rn(v1.z), __float2half_rn(v1.w)};
    return *(const uint4*)h;
}
__device__ __forceinline__ uint2 pack4(const float4 v) {
    __half h[4] = {__float2half_rn(v.x), __float2half_rn(v.y),
                   __float2half_rn(v.z), __float2half_rn(v.w)};
    return *(const uint2*)h;
}

// ---------------- convert x: gather sorted rows -> fp16 ----------------
__global__ void convert_x(const float* __restrict__ x) {
    const int p = blockIdx.x;
    const float4* src = (const float4*)(x + (size_t)g_tok[p] * DD);
    uint4* dst = (uint4*)(g_x16 + (size_t)p * DD);
    for (int i = threadIdx.x; i < DD / 8; i += 256)
        dst[i] = pack8(src[2 * i], src[2 * i + 1]);
}

// ================= fused gate+up GEMM (wmma fp16, R7 structure + fp16 A) =================
__global__ __launch_bounds__(256, 2) void gemm_gateup(const float* __restrict__ Wg,
                                                      const float* __restrict__ Wu) {
    __shared__ __align__(16) __half As[2][BM * ALD];      // [buf]; epilogue scratch overlays this
    __shared__ __align__(16) __half Bsm[2][2][BK * BLD];  // [buf][gate/up]

    const int mt = blockIdx.x;
    if (mt >= g_num_tiles) return;
    const int e = g_tile_e[mt];
    const int row0 = g_tile_row0[mt];
    const int cnt = g_tile_cnt[mt];
    const int n0 = blockIdx.y * BN;
    const int tid = threadIdx.x;
    const int wid = tid >> 5;
    const int lane = tid & 31;
    const int wm0 = (wid & 3) * 32;
    const int wn0 = (wid >> 2) * 32;

    // A loader: 128 rows x 2 segments of 8 halves (16B)
    const int lr = tid >> 1, lc = (tid & 1) * 8;
    const int rowc = (lr < cnt) ? lr : 0;
    const __half* pa = g_x16 + (size_t)(row0 + rowc) * DD + lc;
    const int aoff = lr * ALD + lc;
    // B loader: 16 k-rows x 16 chunks of 4 floats
    const int bk = tid >> 4, bn = (tid & 15) * 4;
    const float* pg = Wg + ((size_t)e * DD + bk) * FF + n0 + bn;
    const float* pu = Wu + ((size_t)e * DD + bk) * FF + n0 + bn;
    const int boff = bk * BLD + bn;

    wmma::fragment<wmma::accumulator, 16, 16, 16, float> accg[2][2], accu[2][2];
#pragma unroll
    for (int mi = 0; mi < 2; mi++)
#pragma unroll
        for (int nj = 0; nj < 2; nj++) {
            wmma::fill_fragment(accg[mi][nj], 0.0f);
            wmma::fill_fragment(accu[mi][nj], 0.0f);
        }

    const int NC = DD / BK;  // 128

    // prime buffer 0
    *(uint4*)&As[0][aoff] = *(const uint4*)pa;
    *(uint2*)&Bsm[0][0][boff] = pack4(*(const float4*)pg);
    *(uint2*)&Bsm[0][1][boff] = pack4(*(const float4*)pu);
    __syncthreads();

    for (int c = 0; c < NC; c++) {
        const int buf = c & 1;
        uint4 va;
        float4 vg, vu;
        if (c + 1 < NC) {
            va = *(const uint4*)(pa + (c + 1) * BK);
            vg = *(const float4*)(pg + (size_t)(c + 1) * BK * FF);
            vu = *(const float4*)(pu + (size_t)(c + 1) * BK * FF);
        }

        wmma::fragment<wmma::matrix_a, 16, 16, 16, __half, wmma::row_major> aF[2];
        wmma::fragment<wmma::matrix_b, 16, 16, 16, __half, wmma::row_major> bg[2], bu[2];
#pragma unroll
        for (int mi = 0; mi < 2; mi++)
            wmma::load_matrix_sync(aF[mi], &As[buf][(wm0 + mi * 16) * ALD], ALD);
#pragma unroll
        for (int nj = 0; nj < 2; nj++) {
            wmma::load_matrix_sync(bg[nj], &Bsm[buf][0][wn0 + nj * 16], BLD);
            wmma::load_matrix_sync(bu[nj], &Bsm[buf][1][wn0 + nj * 16], BLD);
        }
#pragma unroll
        for (int mi = 0; mi < 2; mi++)
#pragma unroll
            for (int nj = 0; nj < 2; nj++) {
                wmma::mma_sync(accg[mi][nj], aF[mi], bg[nj], accg[mi][nj]);
                wmma::mma_sync(accu[mi][nj], aF[mi], bu[nj], accu[mi][nj]);
            }

        if (c + 1 < NC) {
            const int nb = (c + 1) & 1;
            *(uint4*)&As[nb][aoff] = va;
            *(uint2*)&Bsm[nb][0][boff] = pack4(vg);
            *(uint2*)&Bsm[nb][1][boff] = pack4(vu);
        }
        __syncthreads();
    }

    // epilogue: h16 = silu(g) * u, via per-warp scratch overlaid on A smem
    float* myscr = (float*)&As[0][0] + wid * (16 * SLD);
    const int er = lane >> 1, ec = (lane & 1) * 8;
#pragma unroll
    for (int mi = 0; mi < 2; mi++)
#pragma unroll
        for (int nj = 0; nj < 2; nj++) {
            float gv[8], uv[8];
            wmma::store_matrix_sync(myscr, accg[mi][nj], SLD, wmma::mem_row_major);
            __syncwarp();
#pragma unroll
            for (int q = 0; q < 8; q++) gv[q] = myscr[er * SLD + ec + q];
            __syncwarp();
            wmma::store_matrix_sync(myscr, accu[mi][nj], SLD, wmma::mem_row_major);
            __syncwarp();
#pragma unroll
            for (int q = 0; q < 8; q++) uv[q] = myscr[er * SLD + ec + q];
            __syncwarp();
            const int rin = wm0 + mi * 16 + er;
            if (rin < cnt) {
                __half o[8];
#pragma unroll
                for (int q = 0; q < 8; q++)
                    o[q] = __float2half_rn((gv[q] / (1.0f + __expf(-gv[q]))) * uv[q]);
                *(uint4*)(g_h16 + (size_t)(row0 + rin) * FF + n0 + wn0 + nj * 16 + ec) =
                    *(const uint4*)o;
            }
        }
}

// ================= down GEMM (wmma fp16, R7 structure + fp16 A) =================
__global__ __launch_bounds__(256, 2) void gemm_down(const float* __restrict__ Wd) {
    __shared__ __align__(16) __half As[2][BM * ALD];
    __shared__ __align__(16) __half Bsm[2][BK * BLD];

    const int mt = blockIdx.x;
    if (mt >= g_num_tiles) return;
    const int e = g_tile_e[mt];
    const int row0 = g_tile_row0[mt];
    const int cnt = g_tile_cnt[mt];
    const int n0 = blockIdx.y * BN;
    const int tid = threadIdx.x;
    const int wid = tid >> 5;
    const int lane = tid & 31;
    const int wm0 = (wid & 3) * 32;
    const int wn0 = (wid >> 2) * 32;

    const int lr = tid >> 1, lc = (tid & 1) * 8;
    const int rowc = (lr < cnt) ? lr : 0;
    const __half* pa = g_h16 + (size_t)(row0 + rowc) * FF + lc;
    const int aoff = lr * ALD + lc;
    const int bk = tid >> 4, bn = (tid & 15) * 4;
    const float* pb = Wd + ((size_t)e * FF + bk) * DD + n0 + bn;
    const int boff = bk * BLD + bn;

    wmma::fragment<wmma::accumulator, 16, 16, 16, float> acc[2][2];
#pragma unroll
    for (int mi = 0; mi < 2; mi++)
#pragma unroll
        for (int nj = 0; nj < 2; nj++) wmma::fill_fragment(acc[mi][nj], 0.0f);

    const int NC = FF / BK;  // 256

    *(uint4*)&As[0][aoff] = *(const uint4*)pa;
    *(uint2*)&Bsm[0][boff] = pack4(*(const float4*)pb);
    __syncthreads();

    for (int c = 0; c < NC; c++) {
        const int buf = c & 1;
        uint4 va;
        float4 vb;
        if (c + 1 < NC) {
            va = *(const uint4*)(pa + (c + 1) * BK);
            vb = *(const float4*)(pb + (size_t)(c + 1) * BK * DD);
        }

        wmma::fragment<wmma::matrix_a, 16, 16, 16, __half, wmma::row_major> aF[2];
        wmma::fragment<wmma::matrix_b, 16, 16, 16, __half, wmma::row_major> bd[2];
#pragma unroll
        for (int mi = 0; mi < 2; mi++)
            wmma::load_matrix_sync(aF[mi], &As[buf][(wm0 + mi * 16) * ALD], ALD);
#pragma unroll
        for (int nj = 0; nj < 2; nj++)
            wmma::load_matrix_sync(bd[nj], &Bsm[buf][wn0 + nj * 16], BLD);
#pragma unroll
        for (int mi = 0; mi < 2; mi++)
#pragma unroll
            for (int nj = 0; nj < 2; nj++)
                wmma::mma_sync(acc[mi][nj], aF[mi], bd[nj], acc[mi][nj]);

        if (c + 1 < NC) {
            const int nb = (c + 1) & 1;
            *(uint4*)&As[nb][aoff] = va;
            *(uint2*)&Bsm[nb][boff] = pack4(vb);
        }
        __syncthreads();
    }

    float* myscr = (float*)&As[0][0] + wid * (16 * SLD);
    const int er = lane >> 1, ec = (lane & 1) * 8;
#pragma unroll
    for (int mi = 0; mi < 2; mi++)
#pragma unroll
        for (int nj = 0; nj < 2; nj++) {
            wmma::store_matrix_sync(myscr, acc[mi][nj], SLD, wmma::mem_row_major);
            __syncwarp();
            float o[8];
#pragma unroll
            for (int q = 0; q < 8; q++) o[q] = myscr[er * SLD + ec + q];
            __syncwarp();
            const int rin = wm0 + mi * 16 + er;
            if (rin < cnt) {
                float* dst = g_down + (size_t)(row0 + rin) * DD + n0 + wn0 + nj * 16 + ec;
                *(float4*)dst = make_float4(o[0], o[1], o[2], o[3]);
                *(float4*)(dst + 4) = make_float4(o[4], o[5], o[6], o[7]);
            }
        }
}

// ---------------- combine (proven) ----------------
__global__ void combine_kernel(const float* __restrict__ rw, float* __restrict__ out) {
    const int i = blockIdx.x * blockDim.x + threadIdx.x;
    if (i >= TT * (DD / 4)) return;
    const int t = i / (DD / 4);
    const int c = (i % (DD / 4)) * 4;
    const int p0 = g_pos[t * 2 + 0];
    const int p1 = g_pos[t * 2 + 1];
    const float w0 = rw[t * 2 + 0];
    const float w1 = rw[t * 2 + 1];
    const float4 a = *(const float4*)&g_down[(size_t)p0 * DD + c];
    const float4 b = *(const float4*)&g_down[(size_t)p1 * DD + c];
    float4 o;
    o.x = w0 * a.x + w1 * b.x;
    o.y = w0 * a.y + w1 * b.y;
    o.z = w0 * a.z + w1 * b.z;
    o.w = w0 * a.w + w1 * b.w;
    *(float4*)&out[(size_t)t * DD + c] = o;
}

extern "C" void kernel_launch(void* const* d_in, const int* in_sizes, int n_in,
                              void* d_out, int out_size) {
    const float* x   = (const float*)d_in[0];
    const float* rw  = (const float*)d_in[1];
    const int*   sel = (const int*)d_in[2];
    const float* Wg  = (const float*)d_in[3];
    const float* Wu  = (const float*)d_in[4];
    const float* Wd  = (const float*)d_in[5];
    float* out = (float*)d_out;

    setup_kernel<<<1, 256>>>(sel);
    convert_x<<<AA, 256>>>(x);
    gemm_gateup<<<dim3(MAX_TILES, FF / BN), 256>>>(Wg, Wu);
    gemm_down<<<dim3(MAX_TILES, DD / BN), 256>>>(Wd);
    combine_kernel<<<(TT * (DD / 4) + 255) / 256, 256>>>(rw, out);
}

// round 10
// speedup vs baseline: 1.4445x; 1.2800x over previous
#include <cuda_runtime.h>
#include <cuda_fp16.h>
#include <mma.h>

using namespace nvcuda;

#define TT 4096
#define DD 2048
#define FF 4096
#define EE 8
#define XX 2
#define AA (TT * XX)

#define BM 128
#define BN 64
#define BK 16
#define ALD 24                        // A smem ldm (halves), 48B rows
#define BLD 72                        // B smem ldm (halves), 144B rows
#define SLD 20                        // scratch ldm (floats)
#define MAX_TILES (AA / BM + EE)      // 72

// ---------------- scratch (device globals; ~160MB) ----------------
__device__ __align__(128) __half g_x16[(size_t)AA * DD];   // sorted x, fp16
__device__ __align__(128) __half g_h16[(size_t)AA * FF];   // silu(g)*u, fp16
__device__ __align__(128) float g_down[(size_t)AA * DD];   // down output, fp32
__device__ int g_tile_e[MAX_TILES];
__device__ int g_tile_row0[MAX_TILES];
__device__ int g_tile_cnt[MAX_TILES];
__device__ int g_num_tiles;
__device__ int g_tok[AA];
__device__ int g_pos[AA];

// ---------------- setup: counting sort + tile table (proven) ----------------
__global__ void setup_kernel(const int* __restrict__ sel) {
    __shared__ int cnt[EE];
    __shared__ int cur[EE];
    const int tid = threadIdx.x;
    if (tid < EE) cnt[tid] = 0;
    __syncthreads();
    for (int a = tid; a < AA; a += blockDim.x) atomicAdd(&cnt[sel[a]], 1);
    __syncthreads();
    if (tid == 0) {
        int o = 0, nt = 0;
        for (int e = 0; e < EE; e++) {
            cur[e] = o;
            const int c = cnt[e];
            for (int m = 0; m < c; m += BM) {
                g_tile_e[nt] = e;
                g_tile_row0[nt] = o + m;
                g_tile_cnt[nt] = (c - m < BM) ? (c - m) : BM;
                nt++;
            }
            o += c;
        }
        g_num_tiles = nt;
    }
    __syncthreads();
    for (int a = tid; a < AA; a += blockDim.x) {
        const int e = sel[a];
        const int p = atomicAdd(&cur[e], 1);
        g_pos[a] = p;
        g_tok[p] = a >> 1;
    }
}

__device__ __forceinline__ uint4 pack8(const float4 v0, const float4 v1) {
    __half h[8] = {__float2half_rn(v0.x), __float2half_rn(v0.y),
                   __float2half_rn(v0.z), __float2half_rn(v0.w),
                   __float2half_rn(v1.x), __float2half_rn(v1.y),
                   __float2half_rn(v1.z), __float2half_rn(v1.w)};
    return *(const uint4*)h;
}
__device__ __forceinline__ uint2 pack4(const float4 v) {
    __half h[4] = {__float2half_rn(v.x), __float2half_rn(v.y),
                   __float2half_rn(v.z), __float2half_rn(v.w)};
    return *(const uint2*)h;
}

// ---------------- convert x: gather sorted rows -> fp16 ----------------
__global__ void convert_x(const float* __restrict__ x) {
    const int p = blockIdx.x;
    const float4* src = (const float4*)(x + (size_t)g_tok[p] * DD);
    uint4* dst = (uint4*)(g_x16 + (size_t)p * DD);
    for (int i = threadIdx.x; i < DD / 8; i += 256)
        dst[i] = pack8(src[2 * i], src[2 * i + 1]);
}

// ================= fused gate+up GEMM (wmma fp16, depth-2 prefetch) =================
__global__ __launch_bounds__(256) void gemm_gateup(const float* __restrict__ Wg,
                                                   const float* __restrict__ Wu) {
    __shared__ __align__(16) __half As[2][BM * ALD];      // [buf]; epilogue scratch overlays
    __shared__ __align__(16) __half Bsm[2][2][BK * BLD];  // [buf][gate/up]

    const int mt = blockIdx.x;
    if (mt >= g_num_tiles) return;
    const int e = g_tile_e[mt];
    const int row0 = g_tile_row0[mt];
    const int cnt = g_tile_cnt[mt];
    const int n0 = blockIdx.y * BN;
    const int tid = threadIdx.x;
    const int wid = tid >> 5;
    const int lane = tid & 31;
    const int wm0 = (wid & 3) * 32;
    const int wn0 = (wid >> 2) * 32;

    // A loader: 128 rows x 2 segments of 8 halves (16B)
    const int lr = tid >> 1, lc = (tid & 1) * 8;
    const int rowc = (lr < cnt) ? lr : 0;
    const __half* pa = g_x16 + (size_t)(row0 + rowc) * DD + lc;
    const int aoff = lr * ALD + lc;
    // B loader: 16 k-rows x 16 chunks of 4 floats
    const int bk = tid >> 4, bn = (tid & 15) * 4;
    const float* pg = Wg + ((size_t)e * DD + bk) * FF + n0 + bn;
    const float* pu = Wu + ((size_t)e * DD + bk) * FF + n0 + bn;
    const int boff = bk * BLD + bn;

    wmma::fragment<wmma::accumulator, 16, 16, 16, float> accg[2][2], accu[2][2];
#pragma unroll
    for (int mi = 0; mi < 2; mi++)
#pragma unroll
        for (int nj = 0; nj < 2; nj++) {
            wmma::fill_fragment(accg[mi][nj], 0.0f);
            wmma::fill_fragment(accu[mi][nj], 0.0f);
        }

    const int NC = DD / BK;  // 128 (even)

    auto compute = [&](int buf) {
        wmma::fragment<wmma::matrix_a, 16, 16, 16, __half, wmma::row_major> aF[2];
        wmma::fragment<wmma::matrix_b, 16, 16, 16, __half, wmma::row_major> bg[2], bu[2];
#pragma unroll
        for (int mi = 0; mi < 2; mi++)
            wmma::load_matrix_sync(aF[mi], &As[buf][(wm0 + mi * 16) * ALD], ALD);
#pragma unroll
        for (int nj = 0; nj < 2; nj++) {
            wmma::load_matrix_sync(bg[nj], &Bsm[buf][0][wn0 + nj * 16], BLD);
            wmma::load_matrix_sync(bu[nj], &Bsm[buf][1][wn0 + nj * 16], BLD);
        }
#pragma unroll
        for (int mi = 0; mi < 2; mi++)
#pragma unroll
            for (int nj = 0; nj < 2; nj++) {
                wmma::mma_sync(accg[mi][nj], aF[mi], bg[nj], accg[mi][nj]);
                wmma::mma_sync(accu[mi][nj], aF[mi], bu[nj], accu[mi][nj]);
            }
    };

    // prologue: chunk 0 direct to buf0; chunk 1 staged in S1
    *(uint4*)&As[0][aoff] = *(const uint4*)pa;
    *(uint2*)&Bsm[0][0][boff] = pack4(*(const float4*)pg);
    *(uint2*)&Bsm[0][1][boff] = pack4(*(const float4*)pu);
    uint4 aS1 = *(const uint4*)(pa + BK);
    float4 gS1 = *(const float4*)(pg + (size_t)BK * FF);
    float4 uS1 = *(const float4*)(pu + (size_t)BK * FF);
    uint4 aS0;
    float4 gS0, uS0;
    __syncthreads();

    for (int c = 0; c < NC; c += 2) {
        // even chunk c: read buf0; prefetch c+2 into S0; commit S1 (chunk c+1) to buf1
        if (c + 2 < NC) {
            aS0 = *(const uint4*)(pa + (c + 2) * BK);
            gS0 = *(const float4*)(pg + (size_t)(c + 2) * BK * FF);
            uS0 = *(const float4*)(pu + (size_t)(c + 2) * BK * FF);
        }
        compute(0);
        *(uint4*)&As[1][aoff] = aS1;
        *(uint2*)&Bsm[1][0][boff] = pack4(gS1);
        *(uint2*)&Bsm[1][1][boff] = pack4(uS1);
        __syncthreads();

        // odd chunk c+1: read buf1; prefetch c+3 into S1; commit S0 (chunk c+2) to buf0
        if (c + 3 < NC) {
            aS1 = *(const uint4*)(pa + (c + 3) * BK);
            gS1 = *(const float4*)(pg + (size_t)(c + 3) * BK * FF);
            uS1 = *(const float4*)(pu + (size_t)(c + 3) * BK * FF);
        }
        compute(1);
        if (c + 2 < NC) {
            *(uint4*)&As[0][aoff] = aS0;
            *(uint2*)&Bsm[0][0][boff] = pack4(gS0);
            *(uint2*)&Bsm[0][1][boff] = pack4(uS0);
        }
        __syncthreads();
    }

    // epilogue: h16 = silu(g) * u, via per-warp scratch overlaid on A smem
    float* myscr = (float*)&As[0][0] + wid * (16 * SLD);
    const int er = lane >> 1, ec = (lane & 1) * 8;
#pragma unroll
    for (int mi = 0; mi < 2; mi++)
#pragma unroll
        for (int nj = 0; nj < 2; nj++) {
            float gv[8], uv[8];
            wmma::store_matrix_sync(myscr, accg[mi][nj], SLD, wmma::mem_row_major);
            __syncwarp();
#pragma unroll
            for (int q = 0; q < 8; q++) gv[q] = myscr[er * SLD + ec + q];
            __syncwarp();
            wmma::store_matrix_sync(myscr, accu[mi][nj], SLD, wmma::mem_row_major);
            __syncwarp();
#pragma unroll
            for (int q = 0; q < 8; q++) uv[q] = myscr[er * SLD + ec + q];
            __syncwarp();
            const int rin = wm0 + mi * 16 + er;
            if (rin < cnt) {
                __half o[8];
#pragma unroll
                for (int q = 0; q < 8; q++)
                    o[q] = __float2half_rn((gv[q] / (1.0f + __expf(-gv[q]))) * uv[q]);
                *(uint4*)(g_h16 + (size_t)(row0 + rin) * FF + n0 + wn0 + nj * 16 + ec) =
                    *(const uint4*)o;
            }
        }
}

// ================= down GEMM (wmma fp16, depth-2 prefetch) =================
__global__ __launch_bounds__(256) void gemm_down(const float* __restrict__ Wd) {
    __shared__ __align__(16) __half As[2][BM * ALD];
    __shared__ __align__(16) __half Bsm[2][BK * BLD];

    const int mt = blockIdx.x;
    if (mt >= g_num_tiles) return;
    const int e = g_tile_e[mt];
    const int row0 = g_tile_row0[mt];
    const int cnt = g_tile_cnt[mt];
    const int n0 = blockIdx.y * BN;
    const int tid = threadIdx.x;
    const int wid = tid >> 5;
    const int lane = tid & 31;
    const int wm0 = (wid & 3) * 32;
    const int wn0 = (wid >> 2) * 32;

    const int lr = tid >> 1, lc = (tid & 1) * 8;
    const int rowc = (lr < cnt) ? lr : 0;
    const __half* pa = g_h16 + (size_t)(row0 + rowc) * FF + lc;
    const int aoff = lr * ALD + lc;
    const int bk = tid >> 4, bn = (tid & 15) * 4;
    const float* pb = Wd + ((size_t)e * FF + bk) * DD + n0 + bn;
    const int boff = bk * BLD + bn;

    wmma::fragment<wmma::accumulator, 16, 16, 16, float> acc[2][2];
#pragma unroll
    for (int mi = 0; mi < 2; mi++)
#pragma unroll
        for (int nj = 0; nj < 2; nj++) wmma::fill_fragment(acc[mi][nj], 0.0f);

    const int NC = FF / BK;  // 256 (even)

    auto compute = [&](int buf) {
        wmma::fragment<wmma::matrix_a, 16, 16, 16, __half, wmma::row_major> aF[2];
        wmma::fragment<wmma::matrix_b, 16, 16, 16, __half, wmma::row_major> bd[2];
#pragma unroll
        for (int mi = 0; mi < 2; mi++)
            wmma::load_matrix_sync(aF[mi], &As[buf][(wm0 + mi * 16) * ALD], ALD);
#pragma unroll
        for (int nj = 0; nj < 2; nj++)
            wmma::load_matrix_sync(bd[nj], &Bsm[buf][wn0 + nj * 16], BLD);
#pragma unroll
        for (int mi = 0; mi < 2; mi++)
#pragma unroll
            for (int nj = 0; nj < 2; nj++)
                wmma::mma_sync(acc[mi][nj], aF[mi], bd[nj], acc[mi][nj]);
    };

    *(uint4*)&As[0][aoff] = *(const uint4*)pa;
    *(uint2*)&Bsm[0][boff] = pack4(*(const float4*)pb);
    uint4 aS1 = *(const uint4*)(pa + BK);
    float4 bS1 = *(const float4*)(pb + (size_t)BK * DD);
    uint4 aS0;
    float4 bS0;
    __syncthreads();

    for (int c = 0; c < NC; c += 2) {
        if (c + 2 < NC) {
            aS0 = *(const uint4*)(pa + (c + 2) * BK);
            bS0 = *(const float4*)(pb + (size_t)(c + 2) * BK * DD);
        }
        compute(0);
        *(uint4*)&As[1][aoff] = aS1;
        *(uint2*)&Bsm[1][boff] = pack4(bS1);
        __syncthreads();

        if (c + 3 < NC) {
            aS1 = *(const uint4*)(pa + (c + 3) * BK);
            bS1 = *(const float4*)(pb + (size_t)(c + 3) * BK * DD);
        }
        compute(1);
        if (c + 2 < NC) {
            *(uint4*)&As[0][aoff] = aS0;
            *(uint2*)&Bsm[0][boff] = pack4(bS0);
        }
        __syncthreads();
    }

    float* myscr = (float*)&As[0][0] + wid * (16 * SLD);
    const int er = lane >> 1, ec = (lane & 1) * 8;
#pragma unroll
    for (int mi = 0; mi < 2; mi++)
#pragma unroll
        for (int nj = 0; nj < 2; nj++) {
            wmma::store_matrix_sync(myscr, acc[mi][nj], SLD, wmma::mem_row_major);
            __syncwarp();
            float o[8];
#pragma unroll
            for (int q = 0; q < 8; q++) o[q] = myscr[er * SLD + ec + q];
            __syncwarp();
            const int rin = wm0 + mi * 16 + er;
            if (rin < cnt) {
                float* dst = g_down + (size_t)(row0 + rin) * DD + n0 + wn0 + nj * 16 + ec;
                *(float4*)dst = make_float4(o[0], o[1], o[2], o[3]);
                *(float4*)(dst + 4) = make_float4(o[4], o[5], o[6], o[7]);
            }
        }
}

// ---------------- combine (proven) ----------------
__global__ void combine_kernel(const float* __restrict__ rw, float* __restrict__ out) {
    const int i = blockIdx.x * blockDim.x + threadIdx.x;
    if (i >= TT * (DD / 4)) return;
    const int t = i / (DD / 4);
    const int c = (i % (DD / 4)) * 4;
    const int p0 = g_pos[t * 2 + 0];
    const int p1 = g_pos[t * 2 + 1];
    const float w0 = rw[t * 2 + 0];
    const float w1 = rw[t * 2 + 1];
    const float4 a = *(const float4*)&g_down[(size_t)p0 * DD + c];
    const float4 b = *(const float4*)&g_down[(size_t)p1 * DD + c];
    float4 o;
    o.x = w0 * a.x + w1 * b.x;
    o.y = w0 * a.y + w1 * b.y;
    o.z = w0 * a.z + w1 * b.z;
    o.w = w0 * a.w + w1 * b.w;
    *(float4*)&out[(size_t)t * DD + c] = o;
}

extern "C" void kernel_launch(void* const* d_in, const int* in_sizes, int n_in,
                              void* d_out, int out_size) {
    const float* x   = (const float*)d_in[0];
    const float* rw  = (const float*)d_in[1];
    const int*   sel = (const int*)d_in[2];
    const float* Wg  = (const float*)d_in[3];
    const float* Wu  = (const float*)d_in[4];
    const float* Wd  = (const float*)d_in[5];
    float* out = (float*)d_out;

    setup_kernel<<<1, 256>>>(sel);
    convert_x<<<AA, 256>>>(x);
    gemm_gateup<<<dim3(MAX_TILES, FF / BN), 256>>>(Wg, Wu);
    gemm_down<<<dim3(MAX_TILES, DD / BN), 256>>>(Wd);
    combine_kernel<<<(TT * (DD / 4) + 255) / 256, 256>>>(rw, out);
}

// round 11
// speedup vs baseline: 1.5332x; 1.0614x over previous
#include <cuda_runtime.h>
#include <cuda_fp16.h>
#include <mma.h>

using namespace nvcuda;

#define TT 4096
#define DD 2048
#define FF 4096
#define EE 8
#define XX 2
#define AA (TT * XX)

#define BM 128
#define BN 64
#define BK 16
#define ALD 24                        // A smem ldm (halves), 48B rows
#define BLD 72                        // B smem ldm (halves) for BN=64
#define DN 128                        // down-GEMM BN
#define DBLD 136                      // down-GEMM B smem ldm (halves), 272B rows
#define SLD 20                        // scratch ldm (floats)
#define MAX_TILES (AA / BM + EE)      // 72

// ---------------- scratch (device globals; ~160MB) ----------------
__device__ __align__(128) __half g_x16[(size_t)AA * DD];   // sorted x, fp16
__device__ __align__(128) __half g_h16[(size_t)AA * FF];   // silu(g)*u, fp16
__device__ __align__(128) float g_down[(size_t)AA * DD];   // down output, fp32
__device__ int g_tile_e[MAX_TILES];
__device__ int g_tile_row0[MAX_TILES];
__device__ int g_tile_cnt[MAX_TILES];
__device__ int g_num_tiles;
__device__ int g_tok[AA];
__device__ int g_pos[AA];

// ---------------- setup: counting sort + tile table (proven) ----------------
__global__ void setup_kernel(const int* __restrict__ sel) {
    __shared__ int cnt[EE];
    __shared__ int cur[EE];
    const int tid = threadIdx.x;
    if (tid < EE) cnt[tid] = 0;
    __syncthreads();
    for (int a = tid; a < AA; a += blockDim.x) atomicAdd(&cnt[sel[a]], 1);
    __syncthreads();
    if (tid == 0) {
        int o = 0, nt = 0;
        for (int e = 0; e < EE; e++) {
            cur[e] = o;
            const int c = cnt[e];
            for (int m = 0; m < c; m += BM) {
                g_tile_e[nt] = e;
                g_tile_row0[nt] = o + m;
                g_tile_cnt[nt] = (c - m < BM) ? (c - m) : BM;
                nt++;
            }
            o += c;
        }
        g_num_tiles = nt;
    }
    __syncthreads();
    for (int a = tid; a < AA; a += blockDim.x) {
        const int e = sel[a];
        const int p = atomicAdd(&cur[e], 1);
        g_pos[a] = p;
        g_tok[p] = a >> 1;
    }
}

__device__ __forceinline__ uint4 pack8(const float4 v0, const float4 v1) {
    __half h[8] = {__float2half_rn(v0.x), __float2half_rn(v0.y),
                   __float2half_rn(v0.z), __float2half_rn(v0.w),
                   __float2half_rn(v1.x), __float2half_rn(v1.y),
                   __float2half_rn(v1.z), __float2half_rn(v1.w)};
    return *(const uint4*)h;
}
__device__ __forceinline__ uint2 pack4(const float4 v) {
    __half h[4] = {__float2half_rn(v.x), __float2half_rn(v.y),
                   __float2half_rn(v.z), __float2half_rn(v.w)};
    return *(const uint2*)h;
}

// ---------------- convert x: gather sorted rows -> fp16 ----------------
__global__ void convert_x(const float* __restrict__ x) {
    const int p = blockIdx.x;
    const float4* src = (const float4*)(x + (size_t)g_tok[p] * DD);
    uint4* dst = (uint4*)(g_x16 + (size_t)p * DD);
    for (int i = threadIdx.x; i < DD / 8; i += 256)
        dst[i] = pack8(src[2 * i], src[2 * i + 1]);
}

// ================= fused gate+up GEMM (wmma fp16, depth-2 prefetch) — UNCHANGED R10 =================
__global__ __launch_bounds__(256) void gemm_gateup(const float* __restrict__ Wg,
                                                   const float* __restrict__ Wu) {
    __shared__ __align__(16) __half As[2][BM * ALD];      // [buf]; epilogue scratch overlays
    __shared__ __align__(16) __half Bsm[2][2][BK * BLD];  // [buf][gate/up]

    const int mt = blockIdx.x;
    if (mt >= g_num_tiles) return;
    const int e = g_tile_e[mt];
    const int row0 = g_tile_row0[mt];
    const int cnt = g_tile_cnt[mt];
    const int n0 = blockIdx.y * BN;
    const int tid = threadIdx.x;
    const int wid = tid >> 5;
    const int lane = tid & 31;
    const int wm0 = (wid & 3) * 32;
    const int wn0 = (wid >> 2) * 32;

    const int lr = tid >> 1, lc = (tid & 1) * 8;
    const int rowc = (lr < cnt) ? lr : 0;
    const __half* pa = g_x16 + (size_t)(row0 + rowc) * DD + lc;
    const int aoff = lr * ALD + lc;
    const int bk = tid >> 4, bn = (tid & 15) * 4;
    const float* pg = Wg + ((size_t)e * DD + bk) * FF + n0 + bn;
    const float* pu = Wu + ((size_t)e * DD + bk) * FF + n0 + bn;
    const int boff = bk * BLD + bn;

    wmma::fragment<wmma::accumulator, 16, 16, 16, float> accg[2][2], accu[2][2];
#pragma unroll
    for (int mi = 0; mi < 2; mi++)
#pragma unroll
        for (int nj = 0; nj < 2; nj++) {
            wmma::fill_fragment(accg[mi][nj], 0.0f);
            wmma::fill_fragment(accu[mi][nj], 0.0f);
        }

    const int NC = DD / BK;  // 128

    auto compute = [&](int buf) {
        wmma::fragment<wmma::matrix_a, 16, 16, 16, __half, wmma::row_major> aF[2];
        wmma::fragment<wmma::matrix_b, 16, 16, 16, __half, wmma::row_major> bg[2], bu[2];
#pragma unroll
        for (int mi = 0; mi < 2; mi++)
            wmma::load_matrix_sync(aF[mi], &As[buf][(wm0 + mi * 16) * ALD], ALD);
#pragma unroll
        for (int nj = 0; nj < 2; nj++) {
            wmma::load_matrix_sync(bg[nj], &Bsm[buf][0][wn0 + nj * 16], BLD);
            wmma::load_matrix_sync(bu[nj], &Bsm[buf][1][wn0 + nj * 16], BLD);
        }
#pragma unroll
        for (int mi = 0; mi < 2; mi++)
#pragma unroll
            for (int nj = 0; nj < 2; nj++) {
                wmma::mma_sync(accg[mi][nj], aF[mi], bg[nj], accg[mi][nj]);
                wmma::mma_sync(accu[mi][nj], aF[mi], bu[nj], accu[mi][nj]);
            }
    };

    *(uint4*)&As[0][aoff] = *(const uint4*)pa;
    *(uint2*)&Bsm[0][0][boff] = pack4(*(const float4*)pg);
    *(uint2*)&Bsm[0][1][boff] = pack4(*(const float4*)pu);
    uint4 aS1 = *(const uint4*)(pa + BK);
    float4 gS1 = *(const float4*)(pg + (size_t)BK * FF);
    float4 uS1 = *(const float4*)(pu + (size_t)BK * FF);
    uint4 aS0;
    float4 gS0, uS0;
    __syncthreads();

    for (int c = 0; c < NC; c += 2) {
        if (c + 2 < NC) {
            aS0 = *(const uint4*)(pa + (c + 2) * BK);
            gS0 = *(const float4*)(pg + (size_t)(c + 2) * BK * FF);
            uS0 = *(const float4*)(pu + (size_t)(c + 2) * BK * FF);
        }
        compute(0);
        *(uint4*)&As[1][aoff] = aS1;
        *(uint2*)&Bsm[1][0][boff] = pack4(gS1);
        *(uint2*)&Bsm[1][1][boff] = pack4(uS1);
        __syncthreads();

        if (c + 3 < NC) {
            aS1 = *(const uint4*)(pa + (c + 3) * BK);
            gS1 = *(const float4*)(pg + (size_t)(c + 3) * BK * FF);
            uS1 = *(const float4*)(pu + (size_t)(c + 3) * BK * FF);
        }
        compute(1);
        if (c + 2 < NC) {
            *(uint4*)&As[0][aoff] = aS0;
            *(uint2*)&Bsm[0][0][boff] = pack4(gS0);
            *(uint2*)&Bsm[0][1][boff] = pack4(uS0);
        }
        __syncthreads();
    }

    float* myscr = (float*)&As[0][0] + wid * (16 * SLD);
    const int er = lane >> 1, ec = (lane & 1) * 8;
#pragma unroll
    for (int mi = 0; mi < 2; mi++)
#pragma unroll
        for (int nj = 0; nj < 2; nj++) {
            float gv[8], uv[8];
            wmma::store_matrix_sync(myscr, accg[mi][nj], SLD, wmma::mem_row_major);
            __syncwarp();
#pragma unroll
            for (int q = 0; q < 8; q++) gv[q] = myscr[er * SLD + ec + q];
            __syncwarp();
            wmma::store_matrix_sync(myscr, accu[mi][nj], SLD, wmma::mem_row_major);
            __syncwarp();
#pragma unroll
            for (int q = 0; q < 8; q++) uv[q] = myscr[er * SLD + ec + q];
            __syncwarp();
            const int rin = wm0 + mi * 16 + er;
            if (rin < cnt) {
                __half o[8];
#pragma unroll
                for (int q = 0; q < 8; q++)
                    o[q] = __float2half_rn((gv[q] / (1.0f + __expf(-gv[q]))) * uv[q]);
                *(uint4*)(g_h16 + (size_t)(row0 + rin) * FF + n0 + wn0 + nj * 16 + ec) =
                    *(const uint4*)o;
            }
        }
}

// ================= down GEMM (wmma fp16, depth-2 prefetch, BN=128) =================
__global__ __launch_bounds__(256) void gemm_down(const float* __restrict__ Wd) {
    __shared__ __align__(16) __half As[2][BM * ALD];     // 12KB; epilogue scratch overlays
    __shared__ __align__(16) __half Bsm[2][BK * DBLD];   // 8.5KB

    const int mt = blockIdx.x;
    if (mt >= g_num_tiles) return;
    const int e = g_tile_e[mt];
    const int row0 = g_tile_row0[mt];
    const int cnt = g_tile_cnt[mt];
    const int n0 = blockIdx.y * DN;
    const int tid = threadIdx.x;
    const int wid = tid >> 5;
    const int lane = tid & 31;
    const int wm0 = (wid & 3) * 32;       // 4 warps in m
    const int wn0 = (wid >> 2) * 64;      // 2 warps in n, warp tile 32x64

    const int lr = tid >> 1, lc = (tid & 1) * 8;
    const int rowc = (lr < cnt) ? lr : 0;
    const __half* pa = g_h16 + (size_t)(row0 + rowc) * FF + lc;
    const int aoff = lr * ALD + lc;
    // B loader: 16 k-rows x (128 n / 8-float chunks): 256 threads -> bk=tid>>4, bn=(tid&15)*8
    const int bk = tid >> 4, bn = (tid & 15) * 8;
    const float* pb = Wd + ((size_t)e * FF + bk) * DD + n0 + bn;
    const int boff = bk * DBLD + bn;

    wmma::fragment<wmma::accumulator, 16, 16, 16, float> acc[2][4];
#pragma unroll
    for (int mi = 0; mi < 2; mi++)
#pragma unroll
        for (int nj = 0; nj < 4; nj++) wmma::fill_fragment(acc[mi][nj], 0.0f);

    const int NC = FF / BK;  // 256 (even)

    auto compute = [&](int buf) {
        wmma::fragment<wmma::matrix_a, 16, 16, 16, __half, wmma::row_major> aF[2];
        wmma::fragment<wmma::matrix_b, 16, 16, 16, __half, wmma::row_major> bd[4];
#pragma unroll
        for (int mi = 0; mi < 2; mi++)
            wmma::load_matrix_sync(aF[mi], &As[buf][(wm0 + mi * 16) * ALD], ALD);
#pragma unroll
        for (int nj = 0; nj < 4; nj++)
            wmma::load_matrix_sync(bd[nj], &Bsm[buf][wn0 + nj * 16], DBLD);
#pragma unroll
        for (int mi = 0; mi < 2; mi++)
#pragma unroll
            for (int nj = 0; nj < 4; nj++)
                wmma::mma_sync(acc[mi][nj], aF[mi], bd[nj], acc[mi][nj]);
    };

    *(uint4*)&As[0][aoff] = *(const uint4*)pa;
    *(uint4*)&Bsm[0][boff] = pack8(*(const float4*)pb, *(const float4*)(pb + 4));
    uint4 aS1 = *(const uint4*)(pa + BK);
    float4 bS1a = *(const float4*)(pb + (size_t)BK * DD);
    float4 bS1b = *(const float4*)(pb + (size_t)BK * DD + 4);
    uint4 aS0;
    float4 bS0a, bS0b;
    __syncthreads();

    for (int c = 0; c < NC; c += 2) {
        if (c + 2 < NC) {
            aS0 = *(const uint4*)(pa + (c + 2) * BK);
            bS0a = *(const float4*)(pb + (size_t)(c + 2) * BK * DD);
            bS0b = *(const float4*)(pb + (size_t)(c + 2) * BK * DD + 4);
        }
        compute(0);
        *(uint4*)&As[1][aoff] = aS1;
        *(uint4*)&Bsm[1][boff] = pack8(bS1a, bS1b);
        __syncthreads();

        if (c + 3 < NC) {
            aS1 = *(const uint4*)(pa + (c + 3) * BK);
            bS1a = *(const float4*)(pb + (size_t)(c + 3) * BK * DD);
            bS1b = *(const float4*)(pb + (size_t)(c + 3) * BK * DD + 4);
        }
        compute(1);
        if (c + 2 < NC) {
            *(uint4*)&As[0][aoff] = aS0;
            *(uint4*)&Bsm[0][boff] = pack8(bS0a, bS0b);
        }
        __syncthreads();
    }

    float* myscr = (float*)&As[0][0] + wid * (16 * SLD);
    const int er = lane >> 1, ec = (lane & 1) * 8;
#pragma unroll
    for (int mi = 0; mi < 2; mi++)
#pragma unroll
        for (int nj = 0; nj < 4; nj++) {
            wmma::store_matrix_sync(myscr, acc[mi][nj], SLD, wmma::mem_row_major);
            __syncwarp();
            float o[8];
#pragma unroll
            for (int q = 0; q < 8; q++) o[q] = myscr[er * SLD + ec + q];
            __syncwarp();
            const int rin = wm0 + mi * 16 + er;
            if (rin < cnt) {
                float* dst = g_down + (size_t)(row0 + rin) * DD + n0 + wn0 + nj * 16 + ec;
                *(float4*)dst = make_float4(o[0], o[1], o[2], o[3]);
                *(float4*)(dst + 4) = make_float4(o[4], o[5], o[6], o[7]);
            }
        }
}

// ---------------- combine (proven) ----------------
__global__ void combine_kernel(const float* __restrict__ rw, float* __restrict__ out) {
    const int i = blockIdx.x * blockDim.x + threadIdx.x;
    if (i >= TT * (DD / 4)) return;
    const int t = i / (DD / 4);
    const int c = (i % (DD / 4)) * 4;
    const int p0 = g_pos[t * 2 + 0];
    const int p1 = g_pos[t * 2 + 1];
    const float w0 = rw[t * 2 + 0];
    const float w1 = rw[t * 2 + 1];
    const float4 a = *(const float4*)&g_down[(size_t)p0 * DD + c];
    const float4 b = *(const float4*)&g_down[(size_t)p1 * DD + c];
    float4 o;
    o.x = w0 * a.x + w1 * b.x;
    o.y = w0 * a.y + w1 * b.y;
    o.z = w0 * a.z + w1 * b.z;
    o.w = w0 * a.w + w1 * b.w;
    *(float4*)&out[(size_t)t * DD + c] = o;
}

extern "C" void kernel_launch(void* const* d_in, const int* in_sizes, int n_in,
                              void* d_out, int out_size) {
    const float* x   = (const float*)d_in[0];
    const float* rw  = (const float*)d_in[1];
    const int*   sel = (const int*)d_in[2];
    const float* Wg  = (const float*)d_in[3];
    const float* Wu  = (const float*)d_in[4];
    const float* Wd  = (const float*)d_in[5];
    float* out = (float*)d_out;

    setup_kernel<<<1, 256>>>(sel);
    convert_x<<<AA, 256>>>(x);
    gemm_gateup<<<dim3(MAX_TILES, FF / BN), 256>>>(Wg, Wu);
    gemm_down<<<dim3(MAX_TILES, DD / DN), 256>>>(Wd);
    combine_kernel<<<(TT * (DD / 4) + 255) / 256, 256>>>(rw, out);
}

// round 12
// speedup vs baseline: 1.5543x; 1.0138x over previous
#include <cuda_runtime.h>
#include <cuda_fp16.h>
#include <mma.h>

using namespace nvcuda;

#define TT 4096
#define DD 2048
#define FF 4096
#define EE 8
#define XX 2
#define AA (TT * XX)

#define BM 128
#define BN 64
#define BK 16
#define ALD 24                        // A smem ldm (halves), 48B rows
#define BLD 72                        // B smem ldm (halves) for BN=64
#define DN 128                        // down-GEMM BN
#define DBLD 136                      // down-GEMM B smem ldm (halves), 272B rows
#define DSTG 4                        // down-GEMM cp.async stages
#define SLD 20                        // scratch ldm (floats)
#define MAX_TILES (AA / BM + EE)      // 72

// ---------------- scratch (device globals; ~288MB) ----------------
__device__ __align__(128) __half g_x16[(size_t)AA * DD];     // sorted x, fp16
__device__ __align__(128) __half g_h16[(size_t)AA * FF];     // silu(g)*u, fp16
__device__ __align__(128) __half g_wd16[(size_t)EE * FF * DD];  // Wd fp16 (128MB) — staged statics test
__device__ __align__(128) float g_down[(size_t)AA * DD];     // down output, fp32
__device__ int g_tile_e[MAX_TILES];
__device__ int g_tile_row0[MAX_TILES];
__device__ int g_tile_cnt[MAX_TILES];
__device__ int g_num_tiles;
__device__ int g_tok[AA];
__device__ int g_pos[AA];

// ---------------- helpers ----------------
__device__ __forceinline__ unsigned smem_u32(const void* p) {
    unsigned a;
    asm("{ .reg .u64 t; cvta.to.shared.u64 t, %1; cvt.u32.u64 %0, t; }" : "=r"(a) : "l"(p));
    return a;
}
__device__ __forceinline__ void cp16(unsigned dst, const void* src) {
    asm volatile("cp.async.ca.shared.global [%0], [%1], 16;" :: "r"(dst), "l"(src) : "memory");
}
__device__ __forceinline__ void cp_commit() { asm volatile("cp.async.commit_group;" ::: "memory"); }
__device__ __forceinline__ void cp_wait2() { asm volatile("cp.async.wait_group 2;" ::: "memory"); }

__device__ __forceinline__ uint4 pack8(const float4 v0, const float4 v1) {
    __half h[8] = {__float2half_rn(v0.x), __float2half_rn(v0.y),
                   __float2half_rn(v0.z), __float2half_rn(v0.w),
                   __float2half_rn(v1.x), __float2half_rn(v1.y),
                   __float2half_rn(v1.z), __float2half_rn(v1.w)};
    return *(const uint4*)h;
}
__device__ __forceinline__ uint2 pack4(const float4 v) {
    __half h[4] = {__float2half_rn(v.x), __float2half_rn(v.y),
                   __float2half_rn(v.z), __float2half_rn(v.w)};
    return *(const uint2*)h;
}

// ---------------- setup: counting sort + tile table (proven) ----------------
__global__ void setup_kernel(const int* __restrict__ sel) {
    __shared__ int cnt[EE];
    __shared__ int cur[EE];
    const int tid = threadIdx.x;
    if (tid < EE) cnt[tid] = 0;
    __syncthreads();
    for (int a = tid; a < AA; a += blockDim.x) atomicAdd(&cnt[sel[a]], 1);
    __syncthreads();
    if (tid == 0) {
        int o = 0, nt = 0;
        for (int e = 0; e < EE; e++) {
            cur[e] = o;
            const int c = cnt[e];
            for (int m = 0; m < c; m += BM) {
                g_tile_e[nt] = e;
                g_tile_row0[nt] = o + m;
                g_tile_cnt[nt] = (c - m < BM) ? (c - m) : BM;
                nt++;
            }
            o += c;
        }
        g_num_tiles = nt;
    }
    __syncthreads();
    for (int a = tid; a < AA; a += blockDim.x) {
        const int e = sel[a];
        const int p = atomicAdd(&cur[e], 1);
        g_pos[a] = p;
        g_tok[p] = a >> 1;
    }
}

// ---------------- convert x: gather sorted rows -> fp16 ----------------
__global__ void convert_x(const float* __restrict__ x) {
    const int p = blockIdx.x;
    const float4* src = (const float4*)(x + (size_t)g_tok[p] * DD);
    uint4* dst = (uint4*)(g_x16 + (size_t)p * DD);
    for (int i = threadIdx.x; i < DD / 8; i += 256)
        dst[i] = pack8(src[2 * i], src[2 * i + 1]);
}

// ---------------- convert Wd: elementwise fp32 -> fp16 ----------------
__global__ void convert_wd(const float* __restrict__ Wd) {
    const size_t i = (size_t)blockIdx.x * blockDim.x + threadIdx.x;   // over n/8
    const float4* src = (const float4*)Wd;
    uint4* dst = (uint4*)g_wd16;
    dst[i] = pack8(src[2 * i], src[2 * i + 1]);
}

// ================= fused gate+up GEMM — UNCHANGED R11 (proven) =================
__global__ __launch_bounds__(256) void gemm_gateup(const float* __restrict__ Wg,
                                                   const float* __restrict__ Wu) {
    __shared__ __align__(16) __half As[2][BM * ALD];
    __shared__ __align__(16) __half Bsm[2][2][BK * BLD];

    const int mt = blockIdx.x;
    if (mt >= g_num_tiles) return;
    const int e = g_tile_e[mt];
    const int row0 = g_tile_row0[mt];
    const int cnt = g_tile_cnt[mt];
    const int n0 = blockIdx.y * BN;
    const int tid = threadIdx.x;
    const int wid = tid >> 5;
    const int lane = tid & 31;
    const int wm0 = (wid & 3) * 32;
    const int wn0 = (wid >> 2) * 32;

    const int lr = tid >> 1, lc = (tid & 1) * 8;
    const int rowc = (lr < cnt) ? lr : 0;
    const __half* pa = g_x16 + (size_t)(row0 + rowc) * DD + lc;
    const int aoff = lr * ALD + lc;
    const int bk = tid >> 4, bn = (tid & 15) * 4;
    const float* pg = Wg + ((size_t)e * DD + bk) * FF + n0 + bn;
    const float* pu = Wu + ((size_t)e * DD + bk) * FF + n0 + bn;
    const int boff = bk * BLD + bn;

    wmma::fragment<wmma::accumulator, 16, 16, 16, float> accg[2][2], accu[2][2];
#pragma unroll
    for (int mi = 0; mi < 2; mi++)
#pragma unroll
        for (int nj = 0; nj < 2; nj++) {
            wmma::fill_fragment(accg[mi][nj], 0.0f);
            wmma::fill_fragment(accu[mi][nj], 0.0f);
        }

    const int NC = DD / BK;  // 128

    auto compute = [&](int buf) {
        wmma::fragment<wmma::matrix_a, 16, 16, 16, __half, wmma::row_major> aF[2];
        wmma::fragment<wmma::matrix_b, 16, 16, 16, __half, wmma::row_major> bg[2], bu[2];
#pragma unroll
        for (int mi = 0; mi < 2; mi++)
            wmma::load_matrix_sync(aF[mi], &As[buf][(wm0 + mi * 16) * ALD], ALD);
#pragma unroll
        for (int nj = 0; nj < 2; nj++) {
            wmma::load_matrix_sync(bg[nj], &Bsm[buf][0][wn0 + nj * 16], BLD);
            wmma::load_matrix_sync(bu[nj], &Bsm[buf][1][wn0 + nj * 16], BLD);
        }
#pragma unroll
        for (int mi = 0; mi < 2; mi++)
#pragma unroll
            for (int nj = 0; nj < 2; nj++) {
                wmma::mma_sync(accg[mi][nj], aF[mi], bg[nj], accg[mi][nj]);
                wmma::mma_sync(accu[mi][nj], aF[mi], bu[nj], accu[mi][nj]);
            }
    };

    *(uint4*)&As[0][aoff] = *(const uint4*)pa;
    *(uint2*)&Bsm[0][0][boff] = pack4(*(const float4*)pg);
    *(uint2*)&Bsm[0][1][boff] = pack4(*(const float4*)pu);
    uint4 aS1 = *(const uint4*)(pa + BK);
    float4 gS1 = *(const float4*)(pg + (size_t)BK * FF);
    float4 uS1 = *(const float4*)(pu + (size_t)BK * FF);
    uint4 aS0;
    float4 gS0, uS0;
    __syncthreads();

    for (int c = 0; c < NC; c += 2) {
        if (c + 2 < NC) {
            aS0 = *(const uint4*)(pa + (c + 2) * BK);
            gS0 = *(const float4*)(pg + (size_t)(c + 2) * BK * FF);
            uS0 = *(const float4*)(pu + (size_t)(c + 2) * BK * FF);
        }
        compute(0);
        *(uint4*)&As[1][aoff] = aS1;
        *(uint2*)&Bsm[1][0][boff] = pack4(gS1);
        *(uint2*)&Bsm[1][1][boff] = pack4(uS1);
        __syncthreads();

        if (c + 3 < NC) {
            aS1 = *(const uint4*)(pa + (c + 3) * BK);
            gS1 = *(const float4*)(pg + (size_t)(c + 3) * BK * FF);
            uS1 = *(const float4*)(pu + (size_t)(c + 3) * BK * FF);
        }
        compute(1);
        if (c + 2 < NC) {
            *(uint4*)&As[0][aoff] = aS0;
            *(uint2*)&Bsm[0][0][boff] = pack4(gS0);
            *(uint2*)&Bsm[0][1][boff] = pack4(uS0);
        }
        __syncthreads();
    }

    float* myscr = (float*)&As[0][0] + wid * (16 * SLD);
    const int er = lane >> 1, ec = (lane & 1) * 8;
#pragma unroll
    for (int mi = 0; mi < 2; mi++)
#pragma unroll
        for (int nj = 0; nj < 2; nj++) {
            float gv[8], uv[8];
            wmma::store_matrix_sync(myscr, accg[mi][nj], SLD, wmma::mem_row_major);
            __syncwarp();
#pragma unroll
            for (int q = 0; q < 8; q++) gv[q] = myscr[er * SLD + ec + q];
            __syncwarp();
            wmma::store_matrix_sync(myscr, accu[mi][nj], SLD, wmma::mem_row_major);
            __syncwarp();
#pragma unroll
            for (int q = 0; q < 8; q++) uv[q] = myscr[er * SLD + ec + q];
            __syncwarp();
            const int rin = wm0 + mi * 16 + er;
            if (rin < cnt) {
                __half o[8];
#pragma unroll
                for (int q = 0; q < 8; q++)
                    o[q] = __float2half_rn((gv[q] / (1.0f + __expf(-gv[q]))) * uv[q]);
                *(uint4*)(g_h16 + (size_t)(row0 + rin) * FF + n0 + wn0 + nj * 16 + ec) =
                    *(const uint4*)o;
            }
        }
}

// ================= down GEMM (wmma fp16, 4-stage cp.async, fp16 weights) =================
__global__ __launch_bounds__(256) void gemm_down() {
    __shared__ __align__(16) __half As[DSTG][BM * ALD];     // 4 x 6KB
    __shared__ __align__(16) __half Bsm[DSTG][BK * DBLD];   // 4 x 4.25KB

    const int mt = blockIdx.x;
    if (mt >= g_num_tiles) return;
    const int e = g_tile_e[mt];
    const int row0 = g_tile_row0[mt];
    const int cnt = g_tile_cnt[mt];
    const int n0 = blockIdx.y * DN;
    const int tid = threadIdx.x;
    const int wid = tid >> 5;
    const int lane = tid & 31;
    const int wm0 = (wid & 3) * 32;
    const int wn0 = (wid >> 2) * 64;

    // A loader: 128 rows x 2 x 16B
    const int lr = tid >> 1, lc = (tid & 1) * 8;
    const int rowc = (lr < cnt) ? lr : 0;
    const __half* pa = g_h16 + (size_t)(row0 + rowc) * FF + lc;
    const unsigned aS[DSTG] = {smem_u32(&As[0][lr * ALD + lc]), smem_u32(&As[1][lr * ALD + lc]),
                               smem_u32(&As[2][lr * ALD + lc]), smem_u32(&As[3][lr * ALD + lc])};
    // B loader: 16 k-rows x 16 x 16B (fp16 weights)
    const int bk = tid >> 4, bn = (tid & 15) * 8;
    const __half* pb = g_wd16 + ((size_t)e * FF + bk) * DD + n0 + bn;
    const unsigned bS[DSTG] = {smem_u32(&Bsm[0][bk * DBLD + bn]), smem_u32(&Bsm[1][bk * DBLD + bn]),
                               smem_u32(&Bsm[2][bk * DBLD + bn]), smem_u32(&Bsm[3][bk * DBLD + bn])};

    wmma::fragment<wmma::accumulator, 16, 16, 16, float> acc[2][4];
#pragma unroll
    for (int mi = 0; mi < 2; mi++)
#pragma unroll
        for (int nj = 0; nj < 4; nj++) wmma::fill_fragment(acc[mi][nj], 0.0f);

    const int NC = FF / BK;  // 256

    auto issue = [&](int c) {
        if (c < NC) {
            const int s = c & 3;
            cp16(aS[s], pa + (size_t)c * BK);
            cp16(bS[s], pb + (size_t)c * BK * DD);
        }
        cp_commit();
    };
    auto compute = [&](int buf) {
        wmma::fragment<wmma::matrix_a, 16, 16, 16, __half, wmma::row_major> aF[2];
        wmma::fragment<wmma::matrix_b, 16, 16, 16, __half, wmma::row_major> bd[4];
#pragma unroll
        for (int mi = 0; mi < 2; mi++)
            wmma::load_matrix_sync(aF[mi], &As[buf][(wm0 + mi * 16) * ALD], ALD);
#pragma unroll
        for (int nj = 0; nj < 4; nj++)
            wmma::load_matrix_sync(bd[nj], &Bsm[buf][wn0 + nj * 16], DBLD);
#pragma unroll
        for (int mi = 0; mi < 2; mi++)
#pragma unroll
            for (int nj = 0; nj < 4; nj++)
                wmma::mma_sync(acc[mi][nj], aF[mi], bd[nj], acc[mi][nj]);
    };

    issue(0);
    issue(1);
    issue(2);

    for (int c = 0; c < NC; c++) {
        cp_wait2();
        __syncthreads();           // stage c ready everywhere; all warps done with slot (c-1)&3
        issue(c + 3);              // writes slot (c+3)&3 == (c-1)&3
        compute(c & 3);
    }

    float* myscr = (float*)&As[0][0] + wid * (16 * SLD);
    const int er = lane >> 1, ec = (lane & 1) * 8;
    __syncthreads();
#pragma unroll
    for (int mi = 0; mi < 2; mi++)
#pragma unroll
        for (int nj = 0; nj < 4; nj++) {
            wmma::store_matrix_sync(myscr, acc[mi][nj], SLD, wmma::mem_row_major);
            __syncwarp();
            float o[8];
#pragma unroll
            for (int q = 0; q < 8; q++) o[q] = myscr[er * SLD + ec + q];
            __syncwarp();
            const int rin = wm0 + mi * 16 + er;
            if (rin < cnt) {
                float* dst = g_down + (size_t)(row0 + rin) * DD + n0 + wn0 + nj * 16 + ec;
                *(float4*)dst = make_float4(o[0], o[1], o[2], o[3]);
                *(float4*)(dst + 4) = make_float4(o[4], o[5], o[6], o[7]);
            }
        }
}

// ---------------- combine (proven) ----------------
__global__ void combine_kernel(const float* __restrict__ rw, float* __restrict__ out) {
    const int i = blockIdx.x * blockDim.x + threadIdx.x;
    if (i >= TT * (DD / 4)) return;
    const int t = i / (DD / 4);
    const int c = (i % (DD / 4)) * 4;
    const int p0 = g_pos[t * 2 + 0];
    const int p1 = g_pos[t * 2 + 1];
    const float w0 = rw[t * 2 + 0];
    const float w1 = rw[t * 2 + 1];
    const float4 a = *(const float4*)&g_down[(size_t)p0 * DD + c];
    const float4 b = *(const float4*)&g_down[(size_t)p1 * DD + c];
    float4 o;
    o.x = w0 * a.x + w1 * b.x;
    o.y = w0 * a.y + w1 * b.y;
    o.z = w0 * a.z + w1 * b.z;
    o.w = w0 * a.w + w1 * b.w;
    *(float4*)&out[(size_t)t * DD + c] = o;
}

extern "C" void kernel_launch(void* const* d_in, const int* in_sizes, int n_in,
                              void* d_out, int out_size) {
    const float* x   = (const float*)d_in[0];
    const float* rw  = (const float*)d_in[1];
    const int*   sel = (const int*)d_in[2];
    const float* Wg  = (const float*)d_in[3];
    const float* Wu  = (const float*)d_in[4];
    const float* Wd  = (const float*)d_in[5];
    float* out = (float*)d_out;

    setup_kernel<<<1, 256>>>(sel);
    convert_x<<<AA, 256>>>(x);
    convert_wd<<<(int)(((size_t)EE * FF * DD / 8) / 256), 256>>>(Wd);
    gemm_gateup<<<dim3(MAX_TILES, FF / BN), 256>>>(Wg, Wu);
    gemm_down<<<dim3(MAX_TILES, DD / DN), 256>>>();
    combine_kernel<<<(TT * (DD / 4) + 255) / 256, 256>>>(rw, out);
}